// round 2
// baseline (speedup 1.0000x reference)
#include <cuda_runtime.h>
#include <math.h>

// Problem constants
#define BB   64      // batch
#define NN   512     // nodes
#define RR   64      // r' (RP)
#define FEATD 256    // node features
#define EMBD 128     // embedding
#define TT   8       // MAX_WALK_LEN
#define D0   512     // MLP width (RR*TT)

// ---------------------------------------------------------------------------
// Device scratch (no cudaMalloc allowed)
// ---------------------------------------------------------------------------
__device__ float        g_M[RR * FEATD];             // Wv @ W  [64,256]
__device__ float        g_F1[BB * RR * NN];          // F1      [B,64,512]
__device__ float        g_FnA[BB * RR * NN];         // ping
__device__ float        g_FnB[BB * RR * NN];         // pong
__device__ unsigned int g_adjp[BB * NN * (NN / 32)]; // packed adjacency bits [B][m][n/32]
__device__ float        g_gpart[BB * TT * 2 * RR];   // gate partials per (b,t,tile,r)

// ---------------------------------------------------------------------------
// K0: pack adjacency: bit n of g_adjp[b][m][w] = (adj[b][n][m] != 0), n = w*32+j
// grid (32, 64): blockIdx.x = mt*16 + w ; block 256
// ---------------------------------------------------------------------------
__global__ void k_pack_adj(const int* __restrict__ adj) {
    int b  = blockIdx.y;
    int w  = blockIdx.x & 15;
    int mt = blockIdx.x >> 4;
    int m  = mt * 256 + threadIdx.x;
    const int* base = adj + ((size_t)b * NN + w * 32) * NN + m;
    unsigned int word = 0;
#pragma unroll
    for (int j = 0; j < 32; j++)
        word |= (base[j * NN] != 0 ? 1u : 0u) << j;
    g_adjp[(b * NN + m) * (NN / 32) + w] = word;
}

// ---------------------------------------------------------------------------
// K1: M = Wv[64,128] @ W[128,256]   (tiny)
// grid 64, block 256
// ---------------------------------------------------------------------------
__global__ void k_M(const float* __restrict__ Wv, const float* __restrict__ W) {
    int idx = blockIdx.x * 256 + threadIdx.x;   // 0..16383
    int r = idx >> 8, c = idx & 255;
    float a = 0.f;
#pragma unroll 4
    for (int e = 0; e < EMBD; e++)
        a += Wv[r * EMBD + e] * W[e * FEATD + c];
    g_M[r * FEATD + c] = a;
}

// ---------------------------------------------------------------------------
// K2: F1[b,:,m] = sigmoid(M @ attr[b,m,:]) ; also gate_0 partials
// grid (2, 64) [tile, b], block 256, one column per thread
// dyn smem: M (64KB) + Wg (16KB) + gate stage (2KB)
// ---------------------------------------------------------------------------
#define SM_F1 ((RR * FEATD + RR * RR + 8 * RR) * 4)

__global__ void __launch_bounds__(256, 1)
k_F1(const float* __restrict__ attr, const float* __restrict__ Wg) {
    extern __shared__ float sm[];
    float* smM  = sm;                   // [64][256]
    float* smWg = sm + RR * FEATD;      // [64][64]
    float* smG  = smWg + RR * RR;       // [8][64]

    int b = blockIdx.y, tile = blockIdx.x, tid = threadIdx.x;

    {
        const float4* s = (const float4*)g_M;
        float4* d = (float4*)smM;
        for (int i = tid; i < RR * FEATD / 4; i += 256) d[i] = s[i];
        const float4* s2 = (const float4*)Wg;
        float4* d2 = (float4*)smWg;
        for (int i = tid; i < RR * RR / 4; i += 256) d2[i] = s2[i];
    }
    __syncthreads();

    int m = tile * 256 + tid;
    float acc[RR];
#pragma unroll
    for (int r = 0; r < RR; r++) acc[r] = 0.f;

    const float4* arow = (const float4*)(attr + ((size_t)b * NN + m) * FEATD);
#pragma unroll 1
    for (int k4 = 0; k4 < FEATD / 4; k4++) {
        float4 a = __ldg(&arow[k4]);
        const float4* mc = (const float4*)smM + k4;
#pragma unroll
        for (int r = 0; r < RR; r++) {
            float4 w = mc[r * (FEATD / 4)];
            acc[r] += a.x * w.x + a.y * w.y + a.z * w.z + a.w * w.w;
        }
    }

#pragma unroll
    for (int r = 0; r < RR; r++) {
        float v = 1.f / (1.f + __expf(-acc[r]));
        acc[r] = v;
        g_F1[((size_t)b * RR + r) * NN + m] = v;
    }

    // gate_0 = sum_m sigmoid(Wg @ F1[:,m])
    int lane = tid & 31, wrp = tid >> 5;
#pragma unroll 1
    for (int r = 0; r < RR; r++) {
        const float4* wr = (const float4*)(smWg + r * RR);
        float g = 0.f;
#pragma unroll
        for (int s4 = 0; s4 < RR / 4; s4++) {
            float4 w = wr[s4];
            g += w.x * acc[s4 * 4] + w.y * acc[s4 * 4 + 1] +
                 w.z * acc[s4 * 4 + 2] + w.w * acc[s4 * 4 + 3];
        }
        g = 1.f / (1.f + __expf(-g));
#pragma unroll
        for (int o = 16; o > 0; o >>= 1) g += __shfl_xor_sync(0xffffffffu, g, o);
        if (lane == 0) smG[wrp * RR + r] = g;
    }
    __syncthreads();
    if (tid < RR) {
        float tot = 0.f;
#pragma unroll
        for (int w = 0; w < 8; w++) tot += smG[w * RR + tid];
        g_gpart[((b * TT + 0) * 2 + tile) * RR + tid] = tot;
    }
}

// ---------------------------------------------------------------------------
// K3: one walk iteration (masked attention with online softmax) + gate
// grid (2, 64) [tile, b], block 256, one output column per thread
// dyn smem: Fn (128KB) + WwT (16KB) + Wg (16KB) + adj (16KB) + gate (2KB)
// ---------------------------------------------------------------------------
#define SM_ITER ((RR * NN + RR * RR + RR * RR + 8 * RR) * 4 + 256 * (NN / 32) * 4)

__global__ void __launch_bounds__(256, 1)
k_iter(const float* __restrict__ Ww, const float* __restrict__ Wg, int t) {
    extern __shared__ float sm[];
    float*        smFn  = sm;                                   // [64][512]
    float*        smWwT = sm + RR * NN;                         // [s][r]
    float*        smWg  = smWwT + RR * RR;                      // [r][s]
    unsigned int* smAdj = (unsigned int*)(smWg + RR * RR);      // [256][16]
    float*        smG   = (float*)(smAdj + 256 * (NN / 32));    // [8][64]

    int b = blockIdx.y, tile = blockIdx.x, tid = threadIdx.x;

    const float* Fn_in  = (t == 1) ? g_F1 : ((t & 1) ? g_FnB : g_FnA);
    float*       Fn_out = (t & 1) ? g_FnA : g_FnB;

    {
        const float4* s = (const float4*)(Fn_in + (size_t)b * RR * NN);
        float4* d = (float4*)smFn;
        for (int i = tid; i < RR * NN / 4; i += 256) d[i] = s[i];
        for (int i = tid; i < RR * RR; i += 256) {
            int r = i >> 6, ss = i & 63;
            smWwT[ss * RR + r] = Ww[i];          // transpose Ww
        }
        const float4* s3 = (const float4*)Wg;
        float4* d3 = (float4*)smWg;
        for (int i = tid; i < RR * RR / 4; i += 256) d3[i] = s3[i];
        const uint4* s4p = (const uint4*)(g_adjp + ((size_t)b * NN + tile * 256) * (NN / 32));
        uint4* d4 = (uint4*)smAdj;
        for (int i = tid; i < 256 * (NN / 32) / 4; i += 256) d4[i] = s4p[i];
    }
    __syncthreads();

    int m = tile * 256 + tid;

    // wwf[r] = sum_s Ww[r][s] * Fn[s][m]   (query for this column)
    float wwf[RR];
#pragma unroll
    for (int r = 0; r < RR; r++) wwf[r] = 0.f;
#pragma unroll 1
    for (int s0 = 0; s0 < RR; s0 += 4) {
        float f0 = smFn[(s0 + 0) * NN + m];
        float f1 = smFn[(s0 + 1) * NN + m];
        float f2 = smFn[(s0 + 2) * NN + m];
        float f3 = smFn[(s0 + 3) * NN + m];
        const float4* w0 = (const float4*)(smWwT + (s0 + 0) * RR);
        const float4* w1 = (const float4*)(smWwT + (s0 + 1) * RR);
        const float4* w2 = (const float4*)(smWwT + (s0 + 2) * RR);
        const float4* w3 = (const float4*)(smWwT + (s0 + 3) * RR);
#pragma unroll
        for (int r4 = 0; r4 < RR / 4; r4++) {
            float4 a = w0[r4], bq = w1[r4], c = w2[r4], d = w3[r4];
            wwf[r4 * 4 + 0] += a.x * f0 + bq.x * f1 + c.x * f2 + d.x * f3;
            wwf[r4 * 4 + 1] += a.y * f0 + bq.y * f1 + c.y * f2 + d.y * f3;
            wwf[r4 * 4 + 2] += a.z * f0 + bq.z * f1 + c.z * f2 + d.z * f3;
            wwf[r4 * 4 + 3] += a.w * f0 + bq.w * f1 + c.w * f2 + d.w * f3;
        }
    }

    // online-softmax attention over keys n (chunk of 8)
    float acc[RR];
#pragma unroll
    for (int r = 0; r < RR; r++) acc[r] = 0.f;
    float mx = -1e30f, denom = 0.f;
    unsigned int aw = 0;
    const unsigned int* myadj = smAdj + tid * (NN / 32);

#pragma unroll 1
    for (int n0 = 0; n0 < NN; n0 += 8) {
        if ((n0 & 31) == 0) aw = myadj[n0 >> 5];

        float s0 = 0.f, s1 = 0.f, s2 = 0.f, s3 = 0.f;
        float s4 = 0.f, s5 = 0.f, s6 = 0.f, s7 = 0.f;
#pragma unroll
        for (int r = 0; r < RR; r++) {
            const float4* row = (const float4*)(smFn + r * NN + n0);
            float4 a = row[0], b4 = row[1];
            float w = wwf[r];
            s0 += a.x * w;  s1 += a.y * w;  s2 += a.z * w;  s3 += a.w * w;
            s4 += b4.x * w; s5 += b4.y * w; s6 += b4.z * w; s7 += b4.w * w;
        }
        unsigned int bits = aw >> (n0 & 31);
        if (!(bits & 1u))   s0 = -1e8f;
        if (!(bits & 2u))   s1 = -1e8f;
        if (!(bits & 4u))   s2 = -1e8f;
        if (!(bits & 8u))   s3 = -1e8f;
        if (!(bits & 16u))  s4 = -1e8f;
        if (!(bits & 32u))  s5 = -1e8f;
        if (!(bits & 64u))  s6 = -1e8f;
        if (!(bits & 128u)) s7 = -1e8f;

        float cmx = fmaxf(fmaxf(fmaxf(s0, s1), fmaxf(s2, s3)),
                          fmaxf(fmaxf(s4, s5), fmaxf(s6, s7)));
        if (cmx > mx) {
            float sc = __expf(mx - cmx);
            mx = cmx;
            denom *= sc;
#pragma unroll
            for (int r = 0; r < RR; r++) acc[r] *= sc;
        }
        float p0 = __expf(s0 - mx), p1 = __expf(s1 - mx);
        float p2 = __expf(s2 - mx), p3 = __expf(s3 - mx);
        float p4 = __expf(s4 - mx), p5 = __expf(s5 - mx);
        float p6 = __expf(s6 - mx), p7 = __expf(s7 - mx);
        denom += ((p0 + p1) + (p2 + p3)) + ((p4 + p5) + (p6 + p7));
#pragma unroll
        for (int r = 0; r < RR; r++) {
            const float4* row = (const float4*)(smFn + r * NN + n0);
            float4 a = row[0], b4 = row[1];
            acc[r] += a.x * p0 + a.y * p1 + a.z * p2 + a.w * p3 +
                      b4.x * p4 + b4.y * p5 + b4.z * p6 + b4.w * p7;
        }
    }

    // Fn_new[:,m] = (acc / denom) * F1[:,m] ; write out
    float inv = 1.f / denom;
    const float* f1b  = g_F1 + (size_t)b * RR * NN + m;
    float*       outb = Fn_out + (size_t)b * RR * NN + m;
#pragma unroll
    for (int r = 0; r < RR; r++) {
        float v = acc[r] * inv * f1b[r * NN];
        acc[r] = v;
        outb[r * NN] = v;
    }

    // gate_t = sum_m sigmoid(Wg @ Fn_new[:,m])   (deterministic reduction)
    int lane = tid & 31, wrp = tid >> 5;
#pragma unroll 1
    for (int r = 0; r < RR; r++) {
        const float4* wr = (const float4*)(smWg + r * RR);
        float g = 0.f;
#pragma unroll
        for (int s4 = 0; s4 < RR / 4; s4++) {
            float4 w = wr[s4];
            g += w.x * acc[s4 * 4] + w.y * acc[s4 * 4 + 1] +
                 w.z * acc[s4 * 4 + 2] + w.w * acc[s4 * 4 + 3];
        }
        g = 1.f / (1.f + __expf(-g));
#pragma unroll
        for (int o = 16; o > 0; o >>= 1) g += __shfl_xor_sync(0xffffffffu, g, o);
        if (lane == 0) smG[wrp * RR + r] = g;
    }
    __syncthreads();
    if (tid < RR) {
        float tot = 0.f;
#pragma unroll
        for (int w = 0; w < 8; w++) tot += smG[w * RR + tid];
        g_gpart[((b * TT + t) * 2 + tile) * RR + tid] = tot;
    }
}

// ---------------------------------------------------------------------------
// K4: assemble fT, L2-normalize, 4-layer MLP. grid 16 (4 batches/CTA), block 256
// ---------------------------------------------------------------------------
__device__ __forceinline__ void mlp_layer(const float (*hin)[D0], float (*hout)[D0],
                                          const float* __restrict__ W,
                                          const float* __restrict__ bias,
                                          int Din, int Dout, int tid) {
    for (int i = tid; i < Dout; i += 256) {
        const float4* wr = (const float4*)(W + (size_t)i * Din);
        float a0 = 0.f, a1 = 0.f, a2 = 0.f, a3 = 0.f;
#pragma unroll 4
        for (int k4 = 0; k4 < Din / 4; k4++) {
            float4 w = __ldg(&wr[k4]);
            float4 x0 = *(const float4*)&hin[0][k4 * 4];
            float4 x1 = *(const float4*)&hin[1][k4 * 4];
            float4 x2 = *(const float4*)&hin[2][k4 * 4];
            float4 x3 = *(const float4*)&hin[3][k4 * 4];
            a0 += w.x * x0.x + w.y * x0.y + w.z * x0.z + w.w * x0.w;
            a1 += w.x * x1.x + w.y * x1.y + w.z * x1.z + w.w * x1.w;
            a2 += w.x * x2.x + w.y * x2.y + w.z * x2.z + w.w * x2.w;
            a3 += w.x * x3.x + w.y * x3.y + w.z * x3.z + w.w * x3.w;
        }
        float bi = bias[i];
        hout[0][i] = fmaxf(a0 + bi, 0.f);
        hout[1][i] = fmaxf(a1 + bi, 0.f);
        hout[2][i] = fmaxf(a2 + bi, 0.f);
        hout[3][i] = fmaxf(a3 + bi, 0.f);
    }
}

__global__ void __launch_bounds__(256, 1)
k_mlp(const float* __restrict__ W0, const float* __restrict__ b0,
      const float* __restrict__ W1, const float* __restrict__ b1,
      const float* __restrict__ W2, const float* __restrict__ b2,
      const float* __restrict__ W3, const float* __restrict__ b3,
      float* __restrict__ out) {
    __shared__ float hA[4][D0];
    __shared__ float hB[4][D0];
    __shared__ float smScale[4];
    int tid = threadIdx.x;
    int bbase = blockIdx.x * 4;

    // assemble fT from gate partials (fixed summation order -> deterministic)
    for (int idx = tid; idx < 4 * D0; idx += 256) {
        int bb = idx >> 9, j = idx & 511, t = j >> 6, r = j & 63;
        int g0 = (((bbase + bb) * TT + t) * 2 + 0) * RR + r;
        hA[bb][j] = g_gpart[g0] + g_gpart[g0 + RR];
    }
    __syncthreads();

    int lane = tid & 31, wrp = tid >> 5;
    if (wrp < 4) {
        float ss = 0.f;
        for (int i = lane; i < D0; i += 32) { float v = hA[wrp][i]; ss += v * v; }
#pragma unroll
        for (int o = 16; o > 0; o >>= 1) ss += __shfl_xor_sync(0xffffffffu, ss, o);
        if (lane == 0) smScale[wrp] = 1.f / fmaxf(sqrtf(ss), 1e-12f);
    }
    __syncthreads();
    for (int idx = tid; idx < 4 * D0; idx += 256) {
        int bb = idx >> 9;
        hA[bb][idx & 511] *= smScale[bb];
    }
    __syncthreads();

    mlp_layer(hA, hB, W0, b0, 512, 512, tid); __syncthreads();
    mlp_layer(hB, hA, W1, b1, 512, 512, tid); __syncthreads();
    mlp_layer(hA, hB, W2, b2, 512, 256, tid); __syncthreads();

    // final layer 256 -> 128, no relu, write output
    for (int i = tid; i < 128; i += 256) {
        const float4* wr = (const float4*)(W3 + (size_t)i * 256);
        float a0 = 0.f, a1 = 0.f, a2 = 0.f, a3 = 0.f;
#pragma unroll 4
        for (int k4 = 0; k4 < 64; k4++) {
            float4 w = __ldg(&wr[k4]);
            float4 x0 = *(const float4*)&hB[0][k4 * 4];
            float4 x1 = *(const float4*)&hB[1][k4 * 4];
            float4 x2 = *(const float4*)&hB[2][k4 * 4];
            float4 x3 = *(const float4*)&hB[3][k4 * 4];
            a0 += w.x * x0.x + w.y * x0.y + w.z * x0.z + w.w * x0.w;
            a1 += w.x * x1.x + w.y * x1.y + w.z * x1.z + w.w * x1.w;
            a2 += w.x * x2.x + w.y * x2.y + w.z * x2.z + w.w * x2.w;
            a3 += w.x * x3.x + w.y * x3.y + w.z * x3.z + w.w * x3.w;
        }
        float bi = b3[i];
        out[(bbase + 0) * 128 + i] = a0 + bi;
        out[(bbase + 1) * 128 + i] = a1 + bi;
        out[(bbase + 2) * 128 + i] = a2 + bi;
        out[(bbase + 3) * 128 + i] = a3 + bi;
    }
}

// ---------------------------------------------------------------------------
// launch
// ---------------------------------------------------------------------------
extern "C" void kernel_launch(void* const* d_in, const int* in_sizes, int n_in,
                              void* d_out, int out_size) {
    const float* attr = (const float*)d_in[0];   // [64,512,256]
    const int*   adj  = (const int*)d_in[1];     // [64,512,512]
    const float* W    = (const float*)d_in[2];   // [128,256]
    const float* Wv   = (const float*)d_in[3];   // [64,128]
    const float* Ww   = (const float*)d_in[4];   // [64,64]
    const float* Wg   = (const float*)d_in[5];   // [64,64]
    const float* W0   = (const float*)d_in[6];
    const float* b0   = (const float*)d_in[7];
    const float* W1   = (const float*)d_in[8];
    const float* b1   = (const float*)d_in[9];
    const float* W2   = (const float*)d_in[10];
    const float* b2   = (const float*)d_in[11];
    const float* W3   = (const float*)d_in[12];
    const float* b3   = (const float*)d_in[13];
    float* out = (float*)d_out;

    cudaFuncSetAttribute(k_F1,   cudaFuncAttributeMaxDynamicSharedMemorySize, SM_F1);
    cudaFuncSetAttribute(k_iter, cudaFuncAttributeMaxDynamicSharedMemorySize, SM_ITER);

    k_pack_adj<<<dim3(32, 64), 256>>>(adj);
    k_M<<<64, 256>>>(Wv, W);
    k_F1<<<dim3(2, 64), 256, SM_F1>>>(attr, Wg);
    for (int t = 1; t < TT; t++)
        k_iter<<<dim3(2, 64), 256, SM_ITER>>>(Ww, Wg, t);
    k_mlp<<<16, 256>>>(W0, b0, W1, b1, W2, b2, W3, b3, out);
}

// round 4
// speedup vs baseline: 3.0880x; 3.0880x over previous
#include <cuda_runtime.h>
#include <math.h>

// Problem constants
#define BB   64      // batch
#define NN   512     // nodes
#define RR   64      // r' (RP)
#define FEATD 256    // node features
#define EMBD 128     // embedding
#define TT   8       // MAX_WALK_LEN
#define D0   512     // MLP width (RR*TT)

// ---------------------------------------------------------------------------
// Device scratch (no cudaMalloc allowed)
// ---------------------------------------------------------------------------
__device__ float        g_M[RR * FEATD];             // Wv @ W  [64,256]
__device__ float        g_F1[BB * RR * NN];          // F1      [B,64,512]
__device__ float        g_FnA[BB * RR * NN];         // ping
__device__ float        g_FnB[BB * RR * NN];         // pong
__device__ unsigned int g_adjp[BB * NN * (NN / 32)]; // packed adjacency bits [B][m][n/32]
__device__ float        g_gpart[BB * TT * 2 * RR];   // gate partials per (b,t,tile,r)

// ---------------------------------------------------------------------------
// K0: pack adjacency: bit n of g_adjp[b][m][w] = (adj[b][n][m] != 0), n = w*32+j
// ---------------------------------------------------------------------------
__global__ void k_pack_adj(const int* __restrict__ adj) {
    int b  = blockIdx.y;
    int w  = blockIdx.x & 15;
    int mt = blockIdx.x >> 4;
    int m  = mt * 256 + threadIdx.x;
    const int* base = adj + ((size_t)b * NN + w * 32) * NN + m;
    unsigned int word = 0;
#pragma unroll
    for (int j = 0; j < 32; j++)
        word |= (base[j * NN] != 0 ? 1u : 0u) << j;
    g_adjp[(b * NN + m) * (NN / 32) + w] = word;
}

// ---------------------------------------------------------------------------
// K1: M = Wv[64,128] @ W[128,256]
// ---------------------------------------------------------------------------
__global__ void k_M(const float* __restrict__ Wv, const float* __restrict__ W) {
    int idx = blockIdx.x * 256 + threadIdx.x;
    int r = idx >> 8, c = idx & 255;
    float a = 0.f;
#pragma unroll 4
    for (int e = 0; e < EMBD; e++)
        a += Wv[r * EMBD + e] * W[e * FEATD + c];
    g_M[r * FEATD + c] = a;
}

// ---------------------------------------------------------------------------
// K2: F1[b,:,m] = sigmoid(M @ attr[b,m,:]) ; also gate_0 partials
// grid (2, 64), block 256, one column per thread
// ---------------------------------------------------------------------------
#define SM_F1 ((RR * FEATD + RR * RR + 8 * RR) * 4)

__global__ void __launch_bounds__(256, 1)
k_F1(const float* __restrict__ attr, const float* __restrict__ Wg) {
    extern __shared__ float sm[];
    float* smM  = sm;                   // [64][256]
    float* smWg = sm + RR * FEATD;      // [64][64]
    float* smG  = smWg + RR * RR;       // [8][64]

    int b = blockIdx.y, tile = blockIdx.x, tid = threadIdx.x;

    {
        const float4* s = (const float4*)g_M;
        float4* d = (float4*)smM;
        for (int i = tid; i < RR * FEATD / 4; i += 256) d[i] = s[i];
        const float4* s2 = (const float4*)Wg;
        float4* d2 = (float4*)smWg;
        for (int i = tid; i < RR * RR / 4; i += 256) d2[i] = s2[i];
    }
    __syncthreads();

    int m = tile * 256 + tid;
    float acc[RR];
#pragma unroll
    for (int r = 0; r < RR; r++) acc[r] = 0.f;

    const float4* arow = (const float4*)(attr + ((size_t)b * NN + m) * FEATD);
#pragma unroll 1
    for (int k4 = 0; k4 < FEATD / 4; k4++) {
        float4 a = __ldg(&arow[k4]);
        const float4* mc = (const float4*)smM + k4;
#pragma unroll
        for (int r = 0; r < RR; r++) {
            float4 w = mc[r * (FEATD / 4)];
            acc[r] += a.x * w.x + a.y * w.y + a.z * w.z + a.w * w.w;
        }
    }

#pragma unroll
    for (int r = 0; r < RR; r++) {
        float v = 1.f / (1.f + __expf(-acc[r]));
        acc[r] = v;
        g_F1[((size_t)b * RR + r) * NN + m] = v;
    }

    int lane = tid & 31, wrp = tid >> 5;
#pragma unroll 1
    for (int r = 0; r < RR; r++) {
        const float4* wr = (const float4*)(smWg + r * RR);
        float g = 0.f;
#pragma unroll
        for (int s4 = 0; s4 < RR / 4; s4++) {
            float4 w = wr[s4];
            g += w.x * acc[s4 * 4] + w.y * acc[s4 * 4 + 1] +
                 w.z * acc[s4 * 4 + 2] + w.w * acc[s4 * 4 + 3];
        }
        g = 1.f / (1.f + __expf(-g));
#pragma unroll
        for (int o = 16; o > 0; o >>= 1) g += __shfl_xor_sync(0xffffffffu, g, o);
        if (lane == 0) smG[wrp * RR + r] = g;
    }
    __syncthreads();
    if (tid < RR) {
        float tot = 0.f;
#pragma unroll
        for (int w = 0; w < 8; w++) tot += smG[w * RR + tid];
        g_gpart[((b * TT + 0) * 2 + tile) * RR + tid] = tot;
    }
}

// ---------------------------------------------------------------------------
// K3: one walk iteration (masked attention, online softmax) + gate
// grid (2, 64), block 512: two threads per column (r-halves), no spills.
// Score pass uses packed fma.rn.f32x2.
// ---------------------------------------------------------------------------
#define SM_ITER ((RR * NN + 2 * RR * RR) * 4 + 256 * (NN / 32) * 4 + 16 * RR * 4)

__global__ void __launch_bounds__(512, 1)
k_iter(const float* __restrict__ Ww, const float* __restrict__ Wg, int t) {
    extern __shared__ float sm[];
    float*        smFn  = sm;                                   // [64][512]
    float*        smWwT = sm + RR * NN;                         // [s][r]
    float*        smWg  = smWwT + RR * RR;                      // [r][s]
    unsigned int* smAdj = (unsigned int*)(smWg + RR * RR);      // [256][16]
    float*        smG   = (float*)(smAdj + 256 * (NN / 32));    // [16][64]

    int b = blockIdx.y, tile = blockIdx.x, tid = threadIdx.x;

    const float* Fn_in  = (t == 1) ? g_F1 : ((t & 1) ? g_FnB : g_FnA);
    float*       Fn_out = (t & 1) ? g_FnA : g_FnB;

    {
        const float4* s = (const float4*)(Fn_in + (size_t)b * RR * NN);
        float4* d = (float4*)smFn;
        for (int i = tid; i < RR * NN / 4; i += 512) d[i] = s[i];
        for (int i = tid; i < RR * RR; i += 512) {
            int r = i >> 6, ss = i & 63;
            smWwT[ss * RR + r] = Ww[i];          // transpose Ww
        }
        const float4* s3 = (const float4*)Wg;
        float4* d3 = (float4*)smWg;
        for (int i = tid; i < RR * RR / 4; i += 512) d3[i] = s3[i];
        const uint4* s4p = (const uint4*)(g_adjp + ((size_t)b * NN + tile * 256) * (NN / 32));
        uint4* d4 = (uint4*)smAdj;
        for (int i = tid; i < 256 * (NN / 32) / 4; i += 512) d4[i] = s4p[i];
    }
    __syncthreads();

    int m     = tile * 256 + (tid >> 1);   // column owned by this thread pair
    int rbase = (tid & 1) * 32;            // this thread's r-half

    // wwf[i] = sum_s Ww[rbase+i][s] * Fn[s][m]   (query half for this column)
    float wwf[32];
#pragma unroll
    for (int i = 0; i < 32; i++) wwf[i] = 0.f;
#pragma unroll 1
    for (int s = 0; s < RR; s++) {
        float fs = smFn[s * NN + m];
        const float4* wr = (const float4*)(smWwT + s * RR + rbase);
#pragma unroll
        for (int i4 = 0; i4 < 8; i4++) {
            float4 w = wr[i4];
            wwf[i4 * 4 + 0] += w.x * fs;
            wwf[i4 * 4 + 1] += w.y * fs;
            wwf[i4 * 4 + 2] += w.z * fs;
            wwf[i4 * 4 + 3] += w.w * fs;
        }
    }

    // online-softmax attention over keys (chunks of 8)
    float acc[32];
#pragma unroll
    for (int i = 0; i < 32; i++) acc[i] = 0.f;
    float mx = -1e30f, denom = 0.f;
    unsigned int aw = 0;
    const unsigned int* myadj = smAdj + (tid >> 1) * (NN / 32);

#pragma unroll 1
    for (int n0 = 0; n0 < NN; n0 += 8) {
        if ((n0 & 31) == 0) aw = myadj[n0 >> 5];

        // partial scores (this r-half), packed f32x2: s01=(n0,n1) ... s67=(n6,n7)
        unsigned long long s01 = 0ull, s23 = 0ull, s45 = 0ull, s67 = 0ull;
#pragma unroll
        for (int i = 0; i < 32; i++) {
            const ulonglong2* row =
                (const ulonglong2*)(smFn + (rbase + i) * NN + n0);
            ulonglong2 fa = row[0];   // keys n0..n3
            ulonglong2 fb = row[1];   // keys n4..n7
            unsigned long long w2;
            asm("mov.b64 %0, {%1, %1};" : "=l"(w2) : "f"(wwf[i]));
            asm("fma.rn.f32x2 %0, %1, %2, %0;" : "+l"(s01) : "l"(fa.x), "l"(w2));
            asm("fma.rn.f32x2 %0, %1, %2, %0;" : "+l"(s23) : "l"(fa.y), "l"(w2));
            asm("fma.rn.f32x2 %0, %1, %2, %0;" : "+l"(s45) : "l"(fb.x), "l"(w2));
            asm("fma.rn.f32x2 %0, %1, %2, %0;" : "+l"(s67) : "l"(fb.y), "l"(w2));
        }
        // combine with pair partner (other r-half)
        {
            unsigned long long o;
            o = __shfl_xor_sync(0xffffffffu, s01, 1);
            asm("add.rn.f32x2 %0, %0, %1;" : "+l"(s01) : "l"(o));
            o = __shfl_xor_sync(0xffffffffu, s23, 1);
            asm("add.rn.f32x2 %0, %0, %1;" : "+l"(s23) : "l"(o));
            o = __shfl_xor_sync(0xffffffffu, s45, 1);
            asm("add.rn.f32x2 %0, %0, %1;" : "+l"(s45) : "l"(o));
            o = __shfl_xor_sync(0xffffffffu, s67, 1);
            asm("add.rn.f32x2 %0, %0, %1;" : "+l"(s67) : "l"(o));
        }
        float s0, s1, s2, s3, s4, s5, s6, s7;
        asm("mov.b64 {%0, %1}, %2;" : "=f"(s0), "=f"(s1) : "l"(s01));
        asm("mov.b64 {%0, %1}, %2;" : "=f"(s2), "=f"(s3) : "l"(s23));
        asm("mov.b64 {%0, %1}, %2;" : "=f"(s4), "=f"(s5) : "l"(s45));
        asm("mov.b64 {%0, %1}, %2;" : "=f"(s6), "=f"(s7) : "l"(s67));

        unsigned int bits = aw >> (n0 & 31);
        if (!(bits & 1u))   s0 = -1e8f;
        if (!(bits & 2u))   s1 = -1e8f;
        if (!(bits & 4u))   s2 = -1e8f;
        if (!(bits & 8u))   s3 = -1e8f;
        if (!(bits & 16u))  s4 = -1e8f;
        if (!(bits & 32u))  s5 = -1e8f;
        if (!(bits & 64u))  s6 = -1e8f;
        if (!(bits & 128u)) s7 = -1e8f;

        float cmx = fmaxf(fmaxf(fmaxf(s0, s1), fmaxf(s2, s3)),
                          fmaxf(fmaxf(s4, s5), fmaxf(s6, s7)));
        if (cmx > mx) {
            float sc = __expf(mx - cmx);
            mx = cmx;
            denom *= sc;
#pragma unroll
            for (int i = 0; i < 32; i++) acc[i] *= sc;
        }
        float p0 = __expf(s0 - mx), p1 = __expf(s1 - mx);
        float p2 = __expf(s2 - mx), p3 = __expf(s3 - mx);
        float p4 = __expf(s4 - mx), p5 = __expf(s5 - mx);
        float p6 = __expf(s6 - mx), p7 = __expf(s7 - mx);
        denom += ((p0 + p1) + (p2 + p3)) + ((p4 + p5) + (p6 + p7));
#pragma unroll
        for (int i = 0; i < 32; i++) {
            const float4* row = (const float4*)(smFn + (rbase + i) * NN + n0);
            float4 a = row[0], b4 = row[1];
            acc[i] += a.x * p0 + a.y * p1 + a.z * p2 + a.w * p3 +
                      b4.x * p4 + b4.y * p5 + b4.z * p6 + b4.w * p7;
        }
    }

    // Fn_new[:,m] = (acc / denom) * F1[:,m] for this r-half; write out
    float inv = 1.f / denom;
    const float* f1b  = g_F1 + (size_t)b * RR * NN + rbase * NN + m;
    float*       outb = Fn_out + (size_t)b * RR * NN + rbase * NN + m;
#pragma unroll
    for (int i = 0; i < 32; i++) {
        float v = acc[i] * inv * f1b[i * NN];
        acc[i] = v;
        outb[i * NN] = v;
    }

    // gate_t = sum_m sigmoid(Wg @ Fn_new[:,m])
    // pair-combine via shfl(1) gives the full dot on both threads; the
    // butterfly over offsets {2,4,8,16} keeps bit0 fixed, so each group
    // contains each of the warp's 16 columns exactly ONCE (no double count).
    int lane = tid & 31, wrp = tid >> 5;
#pragma unroll 1
    for (int r = 0; r < RR; r++) {
        const float4* wr = (const float4*)(smWg + r * RR + rbase);
        float g = 0.f;
#pragma unroll
        for (int s4 = 0; s4 < 8; s4++) {
            float4 w = wr[s4];
            g += w.x * acc[s4 * 4] + w.y * acc[s4 * 4 + 1] +
                 w.z * acc[s4 * 4 + 2] + w.w * acc[s4 * 4 + 3];
        }
        g += __shfl_xor_sync(0xffffffffu, g, 1);       // full dot for this column
        g = 1.f / (1.f + __expf(-g));
#pragma unroll
        for (int o = 2; o < 32; o <<= 1) g += __shfl_xor_sync(0xffffffffu, g, o);
        if (lane == 0) smG[wrp * RR + r] = g;          // sum over 16 distinct columns
    }
    __syncthreads();
    if (tid < RR) {
        float tot = 0.f;
#pragma unroll
        for (int w = 0; w < 16; w++) tot += smG[w * RR + tid];
        g_gpart[((b * TT + t) * 2 + tile) * RR + tid] = tot;
    }
}

// ---------------------------------------------------------------------------
// K4: assemble fT, L2-normalize, 4-layer MLP. grid 16 (4 batches/CTA), block 256
// ---------------------------------------------------------------------------
__device__ __forceinline__ void mlp_layer(const float (*hin)[D0], float (*hout)[D0],
                                          const float* __restrict__ W,
                                          const float* __restrict__ bias,
                                          int Din, int Dout, int tid) {
    for (int i = tid; i < Dout; i += 256) {
        const float4* wr = (const float4*)(W + (size_t)i * Din);
        float a0 = 0.f, a1 = 0.f, a2 = 0.f, a3 = 0.f;
#pragma unroll 4
        for (int k4 = 0; k4 < Din / 4; k4++) {
            float4 w = __ldg(&wr[k4]);
            float4 x0 = *(const float4*)&hin[0][k4 * 4];
            float4 x1 = *(const float4*)&hin[1][k4 * 4];
            float4 x2 = *(const float4*)&hin[2][k4 * 4];
            float4 x3 = *(const float4*)&hin[3][k4 * 4];
            a0 += w.x * x0.x + w.y * x0.y + w.z * x0.z + w.w * x0.w;
            a1 += w.x * x1.x + w.y * x1.y + w.z * x1.z + w.w * x1.w;
            a2 += w.x * x2.x + w.y * x2.y + w.z * x2.z + w.w * x2.w;
            a3 += w.x * x3.x + w.y * x3.y + w.z * x3.z + w.w * x3.w;
        }
        float bi = bias[i];
        hout[0][i] = fmaxf(a0 + bi, 0.f);
        hout[1][i] = fmaxf(a1 + bi, 0.f);
        hout[2][i] = fmaxf(a2 + bi, 0.f);
        hout[3][i] = fmaxf(a3 + bi, 0.f);
    }
}

__global__ void __launch_bounds__(256, 1)
k_mlp(const float* __restrict__ W0, const float* __restrict__ b0,
      const float* __restrict__ W1, const float* __restrict__ b1,
      const float* __restrict__ W2, const float* __restrict__ b2,
      const float* __restrict__ W3, const float* __restrict__ b3,
      float* __restrict__ out) {
    __shared__ float hA[4][D0];
    __shared__ float hB[4][D0];
    __shared__ float smScale[4];
    int tid = threadIdx.x;
    int bbase = blockIdx.x * 4;

    for (int idx = tid; idx < 4 * D0; idx += 256) {
        int bb = idx >> 9, j = idx & 511, t = j >> 6, r = j & 63;
        int g0 = (((bbase + bb) * TT + t) * 2 + 0) * RR + r;
        hA[bb][j] = g_gpart[g0] + g_gpart[g0 + RR];
    }
    __syncthreads();

    int lane = tid & 31, wrp = tid >> 5;
    if (wrp < 4) {
        float ss = 0.f;
        for (int i = lane; i < D0; i += 32) { float v = hA[wrp][i]; ss += v * v; }
#pragma unroll
        for (int o = 16; o > 0; o >>= 1) ss += __shfl_xor_sync(0xffffffffu, ss, o);
        if (lane == 0) smScale[wrp] = 1.f / fmaxf(sqrtf(ss), 1e-12f);
    }
    __syncthreads();
    for (int idx = tid; idx < 4 * D0; idx += 256) {
        int bb = idx >> 9;
        hA[bb][idx & 511] *= smScale[bb];
    }
    __syncthreads();

    mlp_layer(hA, hB, W0, b0, 512, 512, tid); __syncthreads();
    mlp_layer(hB, hA, W1, b1, 512, 512, tid); __syncthreads();
    mlp_layer(hA, hB, W2, b2, 512, 256, tid); __syncthreads();

    for (int i = tid; i < 128; i += 256) {
        const float4* wr = (const float4*)(W3 + (size_t)i * 256);
        float a0 = 0.f, a1 = 0.f, a2 = 0.f, a3 = 0.f;
#pragma unroll 4
        for (int k4 = 0; k4 < 64; k4++) {
            float4 w = __ldg(&wr[k4]);
            float4 x0 = *(const float4*)&hB[0][k4 * 4];
            float4 x1 = *(const float4*)&hB[1][k4 * 4];
            float4 x2 = *(const float4*)&hB[2][k4 * 4];
            float4 x3 = *(const float4*)&hB[3][k4 * 4];
            a0 += w.x * x0.x + w.y * x0.y + w.z * x0.z + w.w * x0.w;
            a1 += w.x * x1.x + w.y * x1.y + w.z * x1.z + w.w * x1.w;
            a2 += w.x * x2.x + w.y * x2.y + w.z * x2.z + w.w * x2.w;
            a3 += w.x * x3.x + w.y * x3.y + w.z * x3.z + w.w * x3.w;
        }
        float bi = b3[i];
        out[(bbase + 0) * 128 + i] = a0 + bi;
        out[(bbase + 1) * 128 + i] = a1 + bi;
        out[(bbase + 2) * 128 + i] = a2 + bi;
        out[(bbase + 3) * 128 + i] = a3 + bi;
    }
}

// ---------------------------------------------------------------------------
// launch
// ---------------------------------------------------------------------------
extern "C" void kernel_launch(void* const* d_in, const int* in_sizes, int n_in,
                              void* d_out, int out_size) {
    const float* attr = (const float*)d_in[0];
    const int*   adj  = (const int*)d_in[1];
    const float* W    = (const float*)d_in[2];
    const float* Wv   = (const float*)d_in[3];
    const float* Ww   = (const float*)d_in[4];
    const float* Wg   = (const float*)d_in[5];
    const float* W0   = (const float*)d_in[6];
    const float* b0   = (const float*)d_in[7];
    const float* W1   = (const float*)d_in[8];
    const float* b1   = (const float*)d_in[9];
    const float* W2   = (const float*)d_in[10];
    const float* b2   = (const float*)d_in[11];
    const float* W3   = (const float*)d_in[12];
    const float* b3   = (const float*)d_in[13];
    float* out = (float*)d_out;

    cudaFuncSetAttribute(k_F1,   cudaFuncAttributeMaxDynamicSharedMemorySize, SM_F1);
    cudaFuncSetAttribute(k_iter, cudaFuncAttributeMaxDynamicSharedMemorySize, SM_ITER);

    k_pack_adj<<<dim3(32, 64), 256>>>(adj);
    k_M<<<64, 256>>>(Wv, W);
    k_F1<<<dim3(2, 64), 256, SM_F1>>>(attr, Wg);
    for (int t = 1; t < TT; t++)
        k_iter<<<dim3(2, 64), 512, SM_ITER>>>(Ww, Wg, t);
    k_mlp<<<16, 256>>>(W0, b0, W1, b1, W2, b2, W3, b3, out);
}